// round 4
// baseline (speedup 1.0000x reference)
#include <cuda_runtime.h>

// Problem constants (fixed by setup_inputs)
#define BB 64      // batch
#define NN 1024    // nodes per graph
#define EE 16384   // edges per graph
#define DD 1024    // input dim
#define CC 128     // channels
#define KMAXC 128  // indeg class cap
#define NKPAD 64   // padded # of indeg classes (actual ~35)
#define ADJS 96    // fixed adjacency stride (max indeg ~40 for Binomial(16384,1/1024))
#define MAXF2 512  // cap on |F2| (actual ~225)
#define MAXF3 72   // cap on |F3| (actual ~16)

#define RELU(x) fmaxf((x), 0.f)

// ---------------- device scratch (no allocations allowed) ----------------
__device__ int   g_adj[NN * ADJS];          // in-adjacency, fixed stride
__device__ int   g_indeg[NN];
__device__ int   g_F2[MAXF2], g_F3[96];
__device__ int   g_slotF2[NN], g_slotF3[NN];
__device__ int   g_slot2cls[NKPAD];
__device__ int   g_nF3, g_nF2, g_nk;
__device__ float g_cnt2[MAXF2 * NKPAD];     // class-count matrix for F2 nodes (zero-padded)
__device__ float g_hw0[BB * CC];            // (relu(x@W_emb+b_emb))@W_conv per graph
__device__ float g_hw1c[BB * NKPAD * CC];   // class table, rows >= nk are zeros
__device__ float g_h2[BB * MAXF2 * CC];     // h2 at F2 nodes, fixed stride 512

// ---------------- fused preprocessing: one block, 1024 threads ----------------
__global__ void __launch_bounds__(1024) k_preproc(const void* ei) {
    __shared__ int s_indeg[NN], s_inF3[NN], s_inF2[NN];
    __shared__ int s_used[KMAXC], s_cls2slot[KMAXC];
    __shared__ int s_e32, s_nF3, s_nF2;
    int t = threadIdx.x;  // == NN
    s_indeg[t] = 0; s_inF3[t] = 0; s_inF2[t] = 0;
    if (t < KMAXC) s_used[t] = 0;
    if (t == 0) {
        s_nF3 = 0; s_nF2 = 0;
        // dtype detect: int32 data reinterpreted as int64 gives out-of-range values
        const long long* p = (const long long*)ei;
        int e32 = 0;
        for (int j = 0; j < 16; j++) { long long v = p[j]; if (v < 0 || v >= (long long)NN) e32 = 1; }
        s_e32 = e32;
    }
    __syncthreads();
    const int e32 = s_e32;
    const int* pi = (const int*)ei;
    const long long* pl = (const long long*)ei;

    // pass 1: adjacency (fixed stride) + degrees + F3 (in-neighbors of node 0)
    for (int e = t; e < EE; e += 1024) {
        int sv = e32 ? pi[e] : (int)pl[e];
        int dv = e32 ? pi[EE + e] : (int)pl[EE + e];
        int pos = atomicAdd(&s_indeg[dv], 1);
        if (pos < ADJS) g_adj[dv * ADJS + pos] = sv;
        if (dv == 0) {
            if (atomicExch(&s_inF3[sv], 1) == 0) {
                int sl = atomicAdd(&s_nF3, 1);
                if (sl < 96) g_F3[sl] = sv;
                g_slotF3[sv] = (sl < MAXF3) ? sl : MAXF3 - 1;
            }
        }
    }
    __syncthreads();
    // indeg classes present
    { int k = min(s_indeg[t], KMAXC - 1); s_used[k] = 1; }
    __syncthreads();
    if (t == 0) {   // deterministic compaction
        int nk = 0;
        for (int k = 0; k < KMAXC; k++)
            if (s_used[k]) { s_cls2slot[k] = (nk < NKPAD) ? nk : NKPAD - 1; if (nk < NKPAD) g_slot2cls[nk] = k; nk++; }
        g_nk = min(nk, NKPAD);
    }
    __syncthreads();
    // F2 = in-neighbors of F3
    int nf3 = min(s_nF3, 96);
    for (int idx = t; idx < nf3 * ADJS; idx += 1024) {
        int w = g_F3[idx / ADJS];
        int j = idx % ADJS;
        if (j < min(s_indeg[w], ADJS)) {
            int src = g_adj[w * ADJS + j];
            if (atomicExch(&s_inF2[src], 1) == 0) {
                int sl = atomicAdd(&s_nF2, 1);
                if (sl < MAXF2) g_F2[sl] = src;
                g_slotF2[src] = (sl < MAXF2) ? sl : MAXF2 - 1;
            }
        }
    }
    __syncthreads();
    // zero count matrix, then build it
    for (int i = t; i < MAXF2 * NKPAD; i += 1024) g_cnt2[i] = 0.f;
    __syncthreads();
    int nf2 = min(s_nF2, MAXF2);
    for (int idx = t; idx < nf2 * ADJS; idx += 1024) {
        int sl = idx / ADJS, j = idx % ADJS;
        int u = g_F2[sl];
        if (j < min(s_indeg[u], ADJS)) {
            int src = g_adj[u * ADJS + j];
            int k = min(s_indeg[src], KMAXC - 1);
            int cs = s_cls2slot[k];
            atomicAdd(&g_cnt2[sl * NKPAD + cs], 1.f);
        }
    }
    g_indeg[t] = s_indeg[t];
    if (t == 0) { g_nF3 = min(nf3, MAXF3); g_nF2 = nf2; }
}

// ---------------- embedding: hw0[b] = relu(x[b]@W_emb + b_emb) @ W_conv ----------------
__global__ void __launch_bounds__(512) k_embed(const float* __restrict__ x,
                                               const float* __restrict__ W_emb,
                                               const float* __restrict__ b_emb,
                                               const float* __restrict__ W_conv) {
    __shared__ float xs[DD];
    __shared__ float part[512];
    __shared__ float es[CC];
    int b = blockIdx.x;
    int t = threadIdx.x;
    for (int i = t; i < DD; i += 512) xs[i] = x[b * DD + i];
    __syncthreads();
    int c = t & (CC - 1);
    int q = t >> 7;
    float acc = 0.f;
    int d0 = q * (DD / 4);
#pragma unroll 8
    for (int d = d0; d < d0 + DD / 4; d++)
        acc += xs[d] * W_emb[d * CC + c];
    part[t] = acc;
    __syncthreads();
    if (q == 0) {
        float e = part[c] + part[c + 128] + part[c + 256] + part[c + 384] + b_emb[c];
        es[c] = RELU(e);
    }
    __syncthreads();
    float a = 0.f;
    int j0 = q * 32;
#pragma unroll 8
    for (int j = j0; j < j0 + 32; j++) a += es[j] * W_conv[j * CC + c];
    part[t] = a;
    __syncthreads();
    if (q == 0) g_hw0[b * CC + c] = part[c] + part[c + 128] + part[c + 256] + part[c + 384];
}

// ---------------- 64x64-tile SGEMM, 256 threads, 4x4 micro ----------------
// MODE 0: hw1c[b*64+slot][c] = (relu(clsval*hw0[b] + bconv)) @ W_conv   (K=128)
//         grid (64, 2): blockIdx.x = b (rows b*64..b*64+63), blockIdx.y = n-half
// MODE 1: h2[b][slot][c] = relu( Cnt[slot] @ hw1c[b] + bconv )          (K=NKPAD)
//         grid (8, 2, 64): blockIdx.x = slot tile, blockIdx.z = b
template <int MODE>
__global__ void __launch_bounds__(256) k_gemm(const float* __restrict__ W,
                                              const float* __restrict__ bconv) {
    __shared__ float As[16][68];
    __shared__ float Ws[16][68];
    __shared__ float hw0s[CC], bcs[CC];
    int t = threadIdx.x;
    int tx = t & 15, ty = t >> 4;
    const int KTOT = (MODE == 0) ? CC : NKPAD;
    int b, m0, nk = 0;
    if (MODE == 0) {
        b = blockIdx.x; m0 = b * 64; nk = g_nk;
        if (t < CC) { hw0s[t] = g_hw0[b * CC + t]; bcs[t] = bconv[t]; }
        __syncthreads();
    } else {
        b = blockIdx.z; m0 = blockIdx.x * 64;
        if (m0 >= g_nF2) return;
    }
    int n0 = blockIdx.y * 64;

    float acc[4][4];
#pragma unroll
    for (int r = 0; r < 4; r++)
#pragma unroll
        for (int c = 0; c < 4; c++) acc[r][c] = 0.f;

    for (int kc = 0; kc < KTOT; kc += 16) {
        // A tile: 64 rows x 16 k, transposed into As[k][m]
        {
            int m = t >> 2, kq = (t & 3) * 4;
            float4 v = make_float4(0.f, 0.f, 0.f, 0.f);
            if (MODE == 0) {
                int slot = m;    // rows are b*64 + slot
                if (slot < nk) {
                    float fk = (float)g_slot2cls[slot];
                    int kk = kc + kq;
                    v.x = RELU(fk * hw0s[kk + 0] + bcs[kk + 0]);
                    v.y = RELU(fk * hw0s[kk + 1] + bcs[kk + 1]);
                    v.z = RELU(fk * hw0s[kk + 2] + bcs[kk + 2]);
                    v.w = RELU(fk * hw0s[kk + 3] + bcs[kk + 3]);
                }
            } else {
                v = *(const float4*)&g_cnt2[(m0 + m) * NKPAD + kc + kq];
            }
            As[kq + 0][m] = v.x; As[kq + 1][m] = v.y;
            As[kq + 2][m] = v.z; As[kq + 3][m] = v.w;
        }
        // B tile: 16 k x 64 cols
        {
            int kk = t >> 4, cq = (t & 15) * 4;
            float4 v;
            if (MODE == 0) v = *(const float4*)&W[(kc + kk) * CC + n0 + cq];
            else           v = *(const float4*)&g_hw1c[((b << 6) + kc + kk) * CC + n0 + cq];
            *(float4*)&Ws[kk][cq] = v;
        }
        __syncthreads();
#pragma unroll
        for (int k = 0; k < 16; k++) {
            float a[4], w[4];
            *(float4*)&a[0] = *(const float4*)&As[k][ty * 4];
            *(float4*)&w[0] = *(const float4*)&Ws[k][tx * 4];
#pragma unroll
            for (int r = 0; r < 4; r++)
#pragma unroll
                for (int c = 0; c < 4; c++) acc[r][c] += a[r] * w[c];
        }
        __syncthreads();
    }
    // epilogue
#pragma unroll
    for (int r = 0; r < 4; r++) {
        int m = ty * 4 + r;
        int col = n0 + tx * 4;
        if (MODE == 0) {
            *(float4*)&g_hw1c[(m0 + m) * CC + col] =
                make_float4(acc[r][0], acc[r][1], acc[r][2], acc[r][3]);
        } else {
            float4 bc4 = *(const float4*)&bconv[col];
            *(float4*)&g_h2[((b << 9) + m0 + m) * CC + col] =
                make_float4(RELU(acc[r][0] + bc4.x), RELU(acc[r][1] + bc4.y),
                            RELU(acc[r][2] + bc4.z), RELU(acc[r][3] + bc4.w));
        }
    }
}

// ---------------- fused tail: conv3 (agg+gemm at F3), conv4 at node0, classifier ----------------
__global__ void __launch_bounds__(128) k_tail(const float* __restrict__ W,
                                              const float* __restrict__ bconv,
                                              const float* __restrict__ Wcls,
                                              const float* __restrict__ bcls,
                                              float* __restrict__ out) {
    __shared__ float rowbuf[4][CC];
    __shared__ float h3s[MAXF3][CC];
    __shared__ float agg4s[CC];
    __shared__ float red[4];
    int b = blockIdx.x;
    int t = threadIdx.x;           // 128
    int warp = t >> 5, lane = t & 31;
    int nF3 = g_nF3;

    // h3[w] = relu( (sum_{u->w} h2[b,u]) @ W + bconv ),  one warp per w
    for (int w = warp; w < nF3; w += 4) {
        int node = g_F3[w];
        int deg = min(g_indeg[node], ADJS);
        float a0 = 0.f, a1 = 0.f, a2 = 0.f, a3 = 0.f;
        for (int j = 0; j < deg; j++) {
            int src = g_adj[node * ADJS + j];
            const float* p = &g_h2[(((unsigned)b << 9) + g_slotF2[src]) * CC];
            a0 += p[lane]; a1 += p[lane + 32]; a2 += p[lane + 64]; a3 += p[lane + 96];
        }
        rowbuf[warp][lane] = a0; rowbuf[warp][lane + 32] = a1;
        rowbuf[warp][lane + 64] = a2; rowbuf[warp][lane + 96] = a3;
        __syncwarp();
        float y0 = 0.f, y1 = 0.f, y2 = 0.f, y3 = 0.f;
#pragma unroll 4
        for (int j = 0; j < CC; j++) {
            float r = rowbuf[warp][j];
            const float* wr = &W[j * CC];
            y0 += r * wr[lane]; y1 += r * wr[lane + 32];
            y2 += r * wr[lane + 64]; y3 += r * wr[lane + 96];
        }
        h3s[w][lane]      = RELU(y0 + bconv[lane]);
        h3s[w][lane + 32] = RELU(y1 + bconv[lane + 32]);
        h3s[w][lane + 64] = RELU(y2 + bconv[lane + 64]);
        h3s[w][lane + 96] = RELU(y3 + bconv[lane + 96]);
        __syncwarp();
    }
    __syncthreads();
    // agg4 = sum over in-edges of node 0 (with multiplicity)
    int deg0 = min(g_indeg[0], ADJS);
    float a = 0.f;
    for (int j = 0; j < deg0; j++) {
        int s3 = g_slotF3[g_adj[j]];
        a += h3s[s3][t];
    }
    agg4s[t] = a;
    __syncthreads();
    float y = 0.f;
#pragma unroll 4
    for (int j = 0; j < CC; j++) y += agg4s[j] * W[j * CC + t];
    y = RELU(y + bconv[t]);
    float v = y * Wcls[t];
#pragma unroll
    for (int o = 16; o; o >>= 1) v += __shfl_xor_sync(0xffffffffu, v, o);
    if (lane == 0) red[warp] = v;
    __syncthreads();
    if (t == 0) out[b] = red[0] + red[1] + red[2] + red[3] + bcls[0];
}

// ---------------- launch ----------------
extern "C" void kernel_launch(void* const* d_in, const int* in_sizes, int n_in,
                              void* d_out, int out_size) {
    const float* x      = (const float*)d_in[0];
    const void*  ei     = d_in[1];
    const float* W_emb  = (const float*)d_in[2];
    const float* b_emb  = (const float*)d_in[3];
    const float* W_conv = (const float*)d_in[4];
    const float* b_conv = (const float*)d_in[5];
    const float* W_cls  = (const float*)d_in[6];
    const float* b_cls  = (const float*)d_in[7];
    float* out = (float*)d_out;

    k_preproc<<<1, 1024>>>(ei);
    k_embed<<<BB, 512>>>(x, W_emb, b_emb, W_conv);
    k_gemm<0><<<dim3(64, 2), 256>>>(W_conv, b_conv);        // hw1c class table
    k_gemm<1><<<dim3(8, 2, 64), 256>>>(W_conv, b_conv);     // h2 = relu(Cnt @ hw1c + b)
    k_tail<<<BB, 128>>>(W_conv, b_conv, W_cls, b_cls, out);
}

// round 6
// speedup vs baseline: 1.5442x; 1.5442x over previous
#include <cuda_runtime.h>

#define BB 64      // batch
#define NN 1024    // nodes
#define EE 16384   // edges
#define DD 1024    // input dim
#define CC 128     // channels
#define KMAXC 128  // indeg class cap
#define NKPAD 64   // padded class count (actual ~35)
#define ADJS 96    // adjacency stride (max indeg ~40)
#define MAXF2 512  // cap |F2| (actual ~225)
#define MAXF3 64   // cap |F3| (actual ~16)
#define RELU(x) fmaxf((x), 0.f)

// ---------------- device scratch ----------------
__device__ int   g_e32;
__device__ int   g_indeg[NN];
__device__ int   g_adj[NN * ADJS];
__device__ int   g_inF3[NN], g_inF2[NN];
__device__ int   g_F3[MAXF3], g_F2[MAXF2];
__device__ int   g_slotF2[NN], g_slotF3[NN];
__device__ int   g_slot2cls[NKPAD];
__device__ int   g_nF3, g_nF2, g_nk;
__device__ float g_cnt2[MAXF2 * NKPAD];     // batch-invariant class-count matrix
__device__ float g_h2[BB * MAXF2 * CC];     // per-graph h2 scratch (same-SM L1 round trip)

// ---------------- preprocessing ----------------
__global__ void k_init(const void* ei) {
    int t = blockIdx.x * blockDim.x + threadIdx.x;
    int nth = gridDim.x * blockDim.x;
    for (int i = t; i < NN; i += nth) { g_indeg[i] = 0; g_inF3[i] = 0; g_inF2[i] = 0; }
    for (int i = t; i < MAXF2 * NKPAD; i += nth) g_cnt2[i] = 0.f;
    if (t == 0) {
        g_nF3 = 0; g_nF2 = 0;
        // dtype detect: int32 data reinterpreted as int64 gives out-of-range values
        const long long* p = (const long long*)ei;
        int e32 = 0;
        for (int j = 0; j < 16; j++) { long long v = p[j]; if (v < 0 || v >= (long long)NN) e32 = 1; }
        g_e32 = e32;
    }
}

__global__ void k_edges(const void* ei) {
    int t = blockIdx.x * blockDim.x + threadIdx.x;
    int nth = gridDim.x * blockDim.x;
    int e32 = g_e32;
    const int* pi = (const int*)ei;
    const long long* pl = (const long long*)ei;
    for (int e = t; e < EE; e += nth) {
        int sv = e32 ? pi[e] : (int)pl[e];
        int dv = e32 ? pi[EE + e] : (int)pl[EE + e];
        int pos = atomicAdd(&g_indeg[dv], 1);
        if (pos < ADJS) g_adj[dv * ADJS + pos] = sv;
        if (dv == 0) {
            if (atomicExch(&g_inF3[sv], 1) == 0) {
                int sl = atomicAdd(&g_nF3, 1);
                if (sl < MAXF3) { g_F3[sl] = sv; g_slotF3[sv] = sl; }
                else g_slotF3[sv] = MAXF3 - 1;
            }
        }
    }
}

__global__ void __launch_bounds__(1024) k_sets() {
    __shared__ int s_used[KMAXC], s_cls2slot[KMAXC];
    int t = threadIdx.x;  // == NN
    if (t < KMAXC) s_used[t] = 0;
    __syncthreads();
    { int k = min(g_indeg[t], KMAXC - 1); s_used[k] = 1; }
    __syncthreads();
    if (t == 0) {   // deterministic class compaction
        int nk = 0;
        for (int k = 0; k < KMAXC; k++) if (s_used[k]) {
            s_cls2slot[k] = (nk < NKPAD) ? nk : NKPAD - 1;
            if (nk < NKPAD) g_slot2cls[nk] = k;
            nk++;
        }
        g_nk = min(nk, NKPAD);
    }
    __syncthreads();
    // F2 = distinct in-neighbors of F3
    int nf3 = min(g_nF3, MAXF3);
    for (int idx = t; idx < nf3 * ADJS; idx += 1024) {
        int w = g_F3[idx / ADJS], j = idx % ADJS;
        if (j < min(g_indeg[w], ADJS)) {
            int src = g_adj[w * ADJS + j];
            if (atomicExch(&g_inF2[src], 1) == 0) {
                int sl = atomicAdd(&g_nF2, 1);
                if (sl < MAXF2) { g_F2[sl] = src; g_slotF2[src] = sl; }
                else g_slotF2[src] = MAXF2 - 1;
            }
        }
    }
    __syncthreads();
    // class-count matrix for F2 nodes (integer-valued -> atomic float exact)
    int nf2 = min(g_nF2, MAXF2);
    for (int idx = t; idx < nf2 * ADJS; idx += 1024) {
        int sl = idx / ADJS, j = idx % ADJS;
        int u = g_F2[sl];
        if (j < min(g_indeg[u], ADJS)) {
            int src = g_adj[u * ADJS + j];
            int cs = s_cls2slot[min(g_indeg[src], KMAXC - 1)];
            atomicAdd(&g_cnt2[sl * NKPAD + cs], 1.f);
        }
    }
}

// ---------------- fully fused per-graph pipeline: 1 block = 1 graph ----------------
// smem layout (floats):
//   sW   [0      .. 16384)   W_conv 128x128
//   sA   [16384  .. 24576)   A1 / cnt-chunk staging / h3 (64x128)
//   sB   [24576  .. 32768)   hw1c / embed partials / warp rowbufs (64x128)
//   xs   [32768  .. 33792)   x[b]
//   e_s  [33792  .. 33920)
//   hw0s [33920  .. 34048)
//   bcs  [34048  .. 34176)
//   agg  [34176  .. 34304)
//   red  [34304  .. 34312)
#define SMEM_MAIN (34312 * 4)

__global__ void __launch_bounds__(256, 1)
k_main(const float* __restrict__ x, const float* __restrict__ W_emb,
       const float* __restrict__ b_emb, const float* __restrict__ W_conv,
       const float* __restrict__ b_conv, const float* __restrict__ Wcls,
       const float* __restrict__ bcls, float* __restrict__ out) {
    extern __shared__ float S[];
    float* sW   = S;
    float* sA   = S + 16384;
    float* sB   = S + 24576;
    float* xs   = S + 32768;
    float* e_s  = S + 33792;
    float* hw0s = S + 33920;
    float* bcs  = S + 34048;
    float* agg  = S + 34176;
    float* red  = S + 34304;
    __shared__ int scls[NKPAD];

    int b = blockIdx.x;
    int t = threadIdx.x;           // 256
    int warp = t >> 5, lane = t & 31;
    int nk = g_nk;
    int nF2 = min(g_nF2, MAXF2);
    int nF3 = min(g_nF3, MAXF3);

    // ---- stage 0: loads ----
    ((float4*)xs)[t] = ((const float4*)(x + b * DD))[t];                 // 1024 floats
    for (int i = t; i < 4096; i += 256) ((float4*)sW)[i] = ((const float4*)W_conv)[i];
    if (t < CC) bcs[t] = b_conv[t];
    if (t < NKPAD) scls[t] = g_slot2cls[t];
    __syncthreads();

    // ---- stage 1: e = relu(x @ W_emb + b_emb);  hw0 = e @ W_conv ----
    {   // thread t: cols lane*4..+4, d-segment warp*128
        float4 acc = make_float4(0.f, 0.f, 0.f, 0.f);
        const float4* We4 = (const float4*)W_emb;
#pragma unroll 4
        for (int d = warp * 128; d < warp * 128 + 128; d++) {
            float xv = xs[d];
            float4 w = We4[d * 32 + lane];
            acc.x += xv * w.x; acc.y += xv * w.y; acc.z += xv * w.z; acc.w += xv * w.w;
        }
        ((float4*)sB)[t] = acc;    // partials: sB[warp*128 + c]
    }
    __syncthreads();
    if (t < CC) {
        float s = b_emb[t];
#pragma unroll
        for (int seg = 0; seg < 8; seg++) s += sB[seg * 128 + t];
        e_s[t] = RELU(s);
    }
    __syncthreads();
    if (t < CC) {
        float a = 0.f;
#pragma unroll 8
        for (int j = 0; j < CC; j++) a += e_s[j] * sW[j * CC + t];
        hw0s[t] = a;
    }
    __syncthreads();

    // ---- stage 2: A1[slot][k] = relu(cls(slot)*hw0[k] + b) (zero-padded rows) ----
    for (int idx = t; idx < NKPAD * CC; idx += 256) {
        int slot = idx >> 7, k = idx & 127;
        float v = 0.f;
        if (slot < nk) v = RELU((float)scls[slot] * hw0s[k] + bcs[k]);
        sA[idx] = v;
    }
    __syncthreads();

    // ---- stage 3: hw1c = A1 @ W  (64x128, K=128) -> sB ----
    {
        int rb = warp * 8, cb = lane * 4;
        float acc[8][4];
#pragma unroll
        for (int r = 0; r < 8; r++)
#pragma unroll
            for (int c = 0; c < 4; c++) acc[r][c] = 0.f;
#pragma unroll 4
        for (int k = 0; k < CC; k++) {
            float4 w4 = *(float4*)&sW[k * CC + cb];
#pragma unroll
            for (int r = 0; r < 8; r++) {
                float a = sA[(rb + r) * CC + k];   // warp-broadcast
                acc[r][0] += a * w4.x; acc[r][1] += a * w4.y;
                acc[r][2] += a * w4.z; acc[r][3] += a * w4.w;
            }
        }
        __syncthreads();
#pragma unroll
        for (int r = 0; r < 8; r++)
            *(float4*)&sB[(rb + r) * CC + cb] =
                make_float4(acc[r][0], acc[r][1], acc[r][2], acc[r][3]);
    }
    __syncthreads();

    // ---- stage 4: h2 = relu(Cnt @ hw1c + b) -> g_h2 (chunks of 64 rows) ----
    {
        int rb = warp * 8, cb = lane * 4;
        for (int r0 = 0; r0 < nF2; r0 += 64) {
            // stage 64x64 cnt chunk into sA (contiguous 4096 floats)
            for (int i = t; i < 1024; i += 256)
                ((float4*)sA)[i] = ((const float4*)&g_cnt2[r0 * NKPAD])[i];
            __syncthreads();
            float acc[8][4];
#pragma unroll
            for (int r = 0; r < 8; r++)
#pragma unroll
                for (int c = 0; c < 4; c++) acc[r][c] = 0.f;
#pragma unroll 4
            for (int k = 0; k < NKPAD; k++) {
                float4 w4 = *(float4*)&sB[k * CC + cb];
#pragma unroll
                for (int r = 0; r < 8; r++) {
                    float a = sA[(rb + r) * NKPAD + k];
                    acc[r][0] += a * w4.x; acc[r][1] += a * w4.y;
                    acc[r][2] += a * w4.z; acc[r][3] += a * w4.w;
                }
            }
            float4 bc4 = *(float4*)&bcs[cb];
#pragma unroll
            for (int r = 0; r < 8; r++) {
                int row = r0 + rb + r;
                if (row < nF2)
                    *(float4*)&g_h2[(((unsigned)b << 9) + row) * CC + cb] =
                        make_float4(RELU(acc[r][0] + bc4.x), RELU(acc[r][1] + bc4.y),
                                    RELU(acc[r][2] + bc4.z), RELU(acc[r][3] + bc4.w));
            }
            __syncthreads();
        }
    }
    __syncthreads();

    // ---- stage 5: h3[f] = relu((sum_{u->F3[f]} h2[u]) @ W + b) -> sA rows ----
    for (int f = warp; f < nF3; f += 8) {
        int node = g_F3[f];
        int deg = min(g_indeg[node], ADJS);
        float a0 = 0.f, a1 = 0.f, a2 = 0.f, a3 = 0.f;
        for (int j = 0; j < deg; j++) {
            int src = g_adj[node * ADJS + j];
            const float* p = &g_h2[(((unsigned)b << 9) + g_slotF2[src]) * CC];
            a0 += p[lane]; a1 += p[lane + 32]; a2 += p[lane + 64]; a3 += p[lane + 96];
        }
        float* rowbuf = &sB[warp * CC];       // sB free now
        rowbuf[lane] = a0; rowbuf[lane + 32] = a1;
        rowbuf[lane + 64] = a2; rowbuf[lane + 96] = a3;
        __syncwarp();
        float y0 = 0.f, y1 = 0.f, y2 = 0.f, y3 = 0.f;
#pragma unroll 4
        for (int j = 0; j < CC; j++) {
            float r = rowbuf[j];
            const float* wr = &sW[j * CC];
            y0 += r * wr[lane]; y1 += r * wr[lane + 32];
            y2 += r * wr[lane + 64]; y3 += r * wr[lane + 96];
        }
        sA[f * CC + lane]      = RELU(y0 + bcs[lane]);
        sA[f * CC + lane + 32] = RELU(y1 + bcs[lane + 32]);
        sA[f * CC + lane + 64] = RELU(y2 + bcs[lane + 64]);
        sA[f * CC + lane + 96] = RELU(y3 + bcs[lane + 96]);
        __syncwarp();
    }
    __syncthreads();

    // ---- stage 6: conv4 at node 0 + classifier ----
    if (t < CC) {
        int deg0 = min(g_indeg[0], ADJS);
        float a = 0.f;
        for (int j = 0; j < deg0; j++)
            a += sA[g_slotF3[g_adj[j]] * CC + t];
        agg[t] = a;
    }
    __syncthreads();
    if (t < CC) {
        float y = 0.f;
#pragma unroll 8
        for (int j = 0; j < CC; j++) y += agg[j] * sW[j * CC + t];
        y = RELU(y + bcs[t]);
        float v = y * Wcls[t];
#pragma unroll
        for (int o = 16; o; o >>= 1) v += __shfl_xor_sync(0xffffffffu, v, o);
        if (lane == 0) red[warp] = v;
    }
    __syncthreads();
    if (t == 0) out[b] = red[0] + red[1] + red[2] + red[3] + bcls[0];
}

// ---------------- launch ----------------
extern "C" void kernel_launch(void* const* d_in, const int* in_sizes, int n_in,
                              void* d_out, int out_size) {
    const float* x      = (const float*)d_in[0];
    const void*  ei     = d_in[1];
    const float* W_emb  = (const float*)d_in[2];
    const float* b_emb  = (const float*)d_in[3];
    const float* W_conv = (const float*)d_in[4];
    const float* b_conv = (const float*)d_in[5];
    const float* W_cls  = (const float*)d_in[6];
    const float* b_cls  = (const float*)d_in[7];
    float* out = (float*)d_out;

    (void)cudaFuncSetAttribute(k_main, cudaFuncAttributeMaxDynamicSharedMemorySize, SMEM_MAIN);

    k_init<<<16, 256>>>(ei);
    k_edges<<<16, 256>>>(ei);
    k_sets<<<1, 1024>>>();
    k_main<<<BB, 256, SMEM_MAIN>>>(x, W_emb, b_emb, W_conv, b_conv, W_cls, b_cls, out);
}

// round 7
// speedup vs baseline: 1.7802x; 1.1528x over previous
#include <cuda_runtime.h>

#define BB 64      // batch
#define NN 1024    // nodes
#define EE 16384   // edges
#define DD 1024    // input dim
#define CC 128     // channels
#define KMAXC 128  // indeg class cap
#define NKPAD 64   // padded class count (actual ~35)
#define ADJS 96    // adjacency stride (max indeg ~40)
#define MAXF2 512  // cap |F2| (actual ~225)
#define MAXF3 64   // cap |F3| (actual ~16)
#define RELU(x) fmaxf((x), 0.f)

// ---------------- device scratch ----------------
__device__ int   g_e32;
__device__ int   g_indeg[NN];
__device__ int   g_adj[NN * ADJS];
__device__ int   g_inF3[NN], g_inF2[NN];
__device__ int   g_F3[MAXF3], g_F2[MAXF2];
__device__ int   g_slotF2[NN], g_slotF3[NN];
__device__ int   g_slot2cls[NKPAD];
__device__ int   g_nF3, g_nF2, g_nk;
__device__ float g_cnt2[MAXF2 * NKPAD];     // batch-invariant class-count matrix
__device__ float g_E[BB * CC];              // embeddings e = relu(x@W_emb+b_emb)
__device__ float g_h2[BB * MAXF2 * CC];     // per-graph h2

// ---------------- preprocessing ----------------
__global__ void k_init(const void* ei) {
    int t = blockIdx.x * blockDim.x + threadIdx.x;
    int nth = gridDim.x * blockDim.x;
    for (int i = t; i < NN; i += nth) { g_indeg[i] = 0; g_inF3[i] = 0; g_inF2[i] = 0; }
    for (int i = t; i < MAXF2 * NKPAD; i += nth) g_cnt2[i] = 0.f;
    if (t == 0) {
        g_nF3 = 0; g_nF2 = 0;
        // dtype detect: int32 data reinterpreted as int64 gives out-of-range values
        const long long* p = (const long long*)ei;
        int e32 = 0;
        for (int j = 0; j < 16; j++) { long long v = p[j]; if (v < 0 || v >= (long long)NN) e32 = 1; }
        g_e32 = e32;
    }
}

__global__ void k_edges(const void* ei) {
    int t = blockIdx.x * blockDim.x + threadIdx.x;
    int nth = gridDim.x * blockDim.x;
    int e32 = g_e32;
    const int* pi = (const int*)ei;
    const long long* pl = (const long long*)ei;
    for (int e = t; e < EE; e += nth) {
        int sv = e32 ? pi[e] : (int)pl[e];
        int dv = e32 ? pi[EE + e] : (int)pl[EE + e];
        int pos = atomicAdd(&g_indeg[dv], 1);
        if (pos < ADJS) g_adj[dv * ADJS + pos] = sv;
        if (dv == 0) {
            if (atomicExch(&g_inF3[sv], 1) == 0) {
                int sl = atomicAdd(&g_nF3, 1);
                if (sl < MAXF3) { g_F3[sl] = sv; g_slotF3[sv] = sl; }
                else g_slotF3[sv] = MAXF3 - 1;
            }
        }
    }
}

__global__ void __launch_bounds__(1024) k_sets() {
    __shared__ int s_used[KMAXC], s_cls2slot[KMAXC];
    int t = threadIdx.x;  // == NN
    if (t < KMAXC) s_used[t] = 0;
    __syncthreads();
    { int k = min(g_indeg[t], KMAXC - 1); s_used[k] = 1; }
    __syncthreads();
    if (t == 0) {   // deterministic class compaction
        int nk = 0;
        for (int k = 0; k < KMAXC; k++) if (s_used[k]) {
            s_cls2slot[k] = (nk < NKPAD) ? nk : NKPAD - 1;
            if (nk < NKPAD) g_slot2cls[nk] = k;
            nk++;
        }
        g_nk = min(nk, NKPAD);
    }
    __syncthreads();
    // F2 = distinct in-neighbors of F3
    int nf3 = min(g_nF3, MAXF3);
    for (int idx = t; idx < nf3 * ADJS; idx += 1024) {
        int w = g_F3[idx / ADJS], j = idx % ADJS;
        if (j < min(g_indeg[w], ADJS)) {
            int src = g_adj[w * ADJS + j];
            if (atomicExch(&g_inF2[src], 1) == 0) {
                int sl = atomicAdd(&g_nF2, 1);
                if (sl < MAXF2) { g_F2[sl] = src; g_slotF2[src] = sl; }
                else g_slotF2[src] = MAXF2 - 1;
            }
        }
    }
    __syncthreads();
    // class-count matrix for F2 nodes (integer counts -> exact in float)
    int nf2 = min(g_nF2, MAXF2);
    for (int idx = t; idx < nf2 * ADJS; idx += 1024) {
        int sl = idx / ADJS, j = idx % ADJS;
        int u = g_F2[sl];
        if (j < min(g_indeg[u], ADJS)) {
            int src = g_adj[u * ADJS + j];
            int cs = s_cls2slot[min(g_indeg[src], KMAXC - 1)];
            atomicAdd(&g_cnt2[sl * NKPAD + cs], 1.f);
        }
    }
}

// ---------------- embedding: E[b] = relu(x[b] @ W_emb + b_emb), grid (64, 4) ----------------
__global__ void __launch_bounds__(256) k_embed2(const float* __restrict__ x,
                                                const float* __restrict__ W_emb,
                                                const float* __restrict__ b_emb) {
    __shared__ float xs[DD];
    __shared__ float part[256];
    int b = blockIdx.x, n0 = blockIdx.y * 32;
    int t = threadIdx.x;
    ((float4*)xs)[t] = ((const float4*)(x + b * DD))[t];
    __syncthreads();
    int c = t & 31, seg = t >> 5;
    float acc = 0.f;
    const float* Wp = W_emb + n0 + c;
#pragma unroll 8
    for (int d = seg * 128; d < seg * 128 + 128; d++)
        acc += xs[d] * Wp[d * CC];
    part[t] = acc;
    __syncthreads();
    if (t < 32) {
        float s = b_emb[n0 + t];
#pragma unroll
        for (int g = 0; g < 8; g++) s += part[g * 32 + t];
        g_E[b * CC + n0 + t] = RELU(s);
    }
}

// ---------------- mid: hw0 -> A1 -> hw1c(half cols) -> h2(half cols), grid (64, 2) ----------------
// smem floats: sWh 8192 | sA1 8192 | sH1 4096 | sCnt 4096 | e_s 128 | hw0f 128 | part 256 | bcs 128
#define SMEM_MID ((8192 + 8192 + 4096 + 4096 + 128 + 128 + 256 + 128) * 4)
__global__ void __launch_bounds__(256, 1) k_mid(const float* __restrict__ W_conv,
                                                const float* __restrict__ b_conv) {
    extern __shared__ float S[];
    float* sWh  = S;           // [128][64]  W_conv columns n0..n0+63
    float* sA1  = S + 8192;    // [64][128]
    float* sH1  = S + 16384;   // [64][64]   hw1c half
    float* sCnt = S + 20480;   // [64][64]
    float* e_s  = S + 24576;
    float* hw0f = S + 24704;
    float* part = S + 24832;
    float* bcs  = S + 25088;
    __shared__ int scls[NKPAD];

    int b = blockIdx.x, n0 = blockIdx.y * 64;
    int t = threadIdx.x, warp = t >> 5, lane = t & 31;
    int nk = g_nk, nF2 = min(g_nF2, MAXF2);

    if (t < CC) { e_s[t] = g_E[b * CC + t]; bcs[t] = b_conv[t]; }
    if (t < NKPAD) scls[t] = g_slot2cls[t];
#pragma unroll
    for (int q = 0; q < 8; q++) {          // W half: 128x64 = 2048 float4
        int idx = t + q * 256;
        int row = idx >> 4, c4 = (idx & 15) * 4;
        *(float4*)&sWh[row * 64 + c4] = *(const float4*)&W_conv[row * CC + n0 + c4];
    }
    __syncthreads();

    // hw0 full (redundant per half), K split over 2 thread groups
    {
        int c = t & 127, kh = t >> 7;
        float a = 0.f;
#pragma unroll 8
        for (int j = kh * 64; j < kh * 64 + 64; j++)
            a += e_s[j] * W_conv[j * CC + c];
        part[t] = a;
    }
    __syncthreads();
    if (t < CC) hw0f[t] = part[t] + part[t + 128];
    __syncthreads();

    // A1[slot][k] = relu(cls*hw0[k] + b) (rows >= nk zero)
    for (int idx = t; idx < NKPAD * CC; idx += 256) {
        int slot = idx >> 7, k = idx & 127;
        float v = 0.f;
        if (slot < nk) v = RELU((float)scls[slot] * hw0f[k] + bcs[k]);
        sA1[idx] = v;
    }
    __syncthreads();

    // hw1c half: [64x64] = sA1[64x128] @ sWh[128x64]
    {
        int rb = warp * 8, cb = lane * 2;
        float acc[8][2] = {};
#pragma unroll 4
        for (int k = 0; k < CC; k++) {
            float2 w2 = *(float2*)&sWh[k * 64 + cb];
#pragma unroll
            for (int r = 0; r < 8; r++) {
                float a = sA1[(rb + r) * CC + k];
                acc[r][0] += a * w2.x; acc[r][1] += a * w2.y;
            }
        }
        __syncthreads();
#pragma unroll
        for (int r = 0; r < 8; r++)
            *(float2*)&sH1[(rb + r) * 64 + cb] = make_float2(acc[r][0], acc[r][1]);
    }
    __syncthreads();

    // h2 half: relu(Cnt @ hw1c_half + b), chunks of 64 rows
    {
        int rb = warp * 8, cb = lane * 2;
        float2 bc2 = *(float2*)&bcs[n0 + cb];
        for (int r0 = 0; r0 < nF2; r0 += 64) {
#pragma unroll
            for (int q = 0; q < 4; q++)
                ((float4*)sCnt)[t + q * 256] = ((const float4*)&g_cnt2[r0 * NKPAD])[t + q * 256];
            __syncthreads();
            float acc[8][2] = {};
#pragma unroll 4
            for (int k = 0; k < NKPAD; k++) {
                float2 w2 = *(float2*)&sH1[k * 64 + cb];
#pragma unroll
                for (int r = 0; r < 8; r++) {
                    float a = sCnt[(rb + r) * NKPAD + k];
                    acc[r][0] += a * w2.x; acc[r][1] += a * w2.y;
                }
            }
#pragma unroll
            for (int r = 0; r < 8; r++) {
                int row = r0 + rb + r;
                if (row < nF2)
                    *(float2*)&g_h2[(((unsigned)b << 9) + row) * CC + n0 + cb] =
                        make_float2(RELU(acc[r][0] + bc2.x), RELU(acc[r][1] + bc2.y));
            }
            __syncthreads();
        }
    }
}

// ---------------- tail: h3 at F3, conv4 at node0, classifier; grid (64) ----------------
// smem floats: sW 16384 | h3s 8192 | rowbuf 1024 | agg 128 | red 8 | bcs 128
#define SMEM_TAIL ((16384 + 8192 + 1024 + 128 + 8 + 128) * 4)
__global__ void __launch_bounds__(256, 1) k_tail(const float* __restrict__ W_conv,
                                                 const float* __restrict__ b_conv,
                                                 const float* __restrict__ Wcls,
                                                 const float* __restrict__ bcls,
                                                 float* __restrict__ out) {
    extern __shared__ float S[];
    float* sW     = S;
    float* h3s    = S + 16384;   // [64][128]
    float* rowbuf = S + 24576;   // [8][128]
    float* agg    = S + 25600;
    float* red    = S + 25728;
    float* bcs    = S + 25736;
    int b = blockIdx.x, t = threadIdx.x, warp = t >> 5, lane = t & 31;
    int nF3 = min(g_nF3, MAXF3);
#pragma unroll
    for (int q = 0; q < 16; q++)
        ((float4*)sW)[t + q * 256] = ((const float4*)W_conv)[t + q * 256];
    if (t < CC) bcs[t] = b_conv[t];
    __syncthreads();

    for (int f = warp; f < nF3; f += 8) {
        int node = g_F3[f];
        int deg = min(g_indeg[node], ADJS);
        float a0 = 0.f, a1 = 0.f, a2 = 0.f, a3 = 0.f;
        for (int j = 0; j < deg; j++) {
            int src = g_adj[node * ADJS + j];
            const float* p = &g_h2[(((unsigned)b << 9) + g_slotF2[src]) * CC];
            a0 += p[lane]; a1 += p[lane + 32]; a2 += p[lane + 64]; a3 += p[lane + 96];
        }
        float* rb = &rowbuf[warp * CC];
        rb[lane] = a0; rb[lane + 32] = a1; rb[lane + 64] = a2; rb[lane + 96] = a3;
        __syncwarp();
        float y0 = 0.f, y1 = 0.f, y2 = 0.f, y3 = 0.f;
#pragma unroll 4
        for (int j = 0; j < CC; j++) {
            float r = rb[j];
            const float* wr = &sW[j * CC];
            y0 += r * wr[lane]; y1 += r * wr[lane + 32];
            y2 += r * wr[lane + 64]; y3 += r * wr[lane + 96];
        }
        h3s[f * CC + lane]      = RELU(y0 + bcs[lane]);
        h3s[f * CC + lane + 32] = RELU(y1 + bcs[lane + 32]);
        h3s[f * CC + lane + 64] = RELU(y2 + bcs[lane + 64]);
        h3s[f * CC + lane + 96] = RELU(y3 + bcs[lane + 96]);
        __syncwarp();
    }
    __syncthreads();

    if (t < CC) {
        int deg0 = min(g_indeg[0], ADJS);
        float a = 0.f;
        for (int j = 0; j < deg0; j++)
            a += h3s[g_slotF3[g_adj[j]] * CC + t];
        agg[t] = a;
    }
    __syncthreads();
    if (t < CC) {
        float y = 0.f;
#pragma unroll 8
        for (int j = 0; j < CC; j++) y += agg[j] * sW[j * CC + t];
        y = RELU(y + bcs[t]);
        float v = y * Wcls[t];
#pragma unroll
        for (int o = 16; o; o >>= 1) v += __shfl_xor_sync(0xffffffffu, v, o);
        if (lane == 0) red[warp] = v;
    }
    __syncthreads();
    if (t == 0) out[b] = red[0] + red[1] + red[2] + red[3] + bcls[0];
}

// ---------------- launch ----------------
extern "C" void kernel_launch(void* const* d_in, const int* in_sizes, int n_in,
                              void* d_out, int out_size) {
    const float* x      = (const float*)d_in[0];
    const void*  ei     = d_in[1];
    const float* W_emb  = (const float*)d_in[2];
    const float* b_emb  = (const float*)d_in[3];
    const float* W_conv = (const float*)d_in[4];
    const float* b_conv = (const float*)d_in[5];
    const float* W_cls  = (const float*)d_in[6];
    const float* b_cls  = (const float*)d_in[7];
    float* out = (float*)d_out;

    (void)cudaFuncSetAttribute(k_mid,  cudaFuncAttributeMaxDynamicSharedMemorySize, SMEM_MID);
    (void)cudaFuncSetAttribute(k_tail, cudaFuncAttributeMaxDynamicSharedMemorySize, SMEM_TAIL);

    k_init<<<16, 256>>>(ei);
    k_edges<<<16, 256>>>(ei);
    k_sets<<<1, 1024>>>();
    k_embed2<<<dim3(BB, 4), 256>>>(x, W_emb, b_emb);
    k_mid<<<dim3(BB, 2), 256, SMEM_MID>>>(W_conv, b_conv);
    k_tail<<<BB, 256, SMEM_TAIL>>>(W_conv, b_conv, W_cls, b_cls, out);
}

// round 8
// speedup vs baseline: 2.0036x; 1.1255x over previous
#include <cuda_runtime.h>

#define BB 64      // batch
#define NN 1024    // nodes
#define EE 16384   // edges
#define DD 1024    // input dim
#define CC 128     // channels
#define KMAXC 128  // indeg class cap
#define NKPAD 64   // padded class count (actual ~35)
#define ADJS 96    // adjacency stride (max indeg ~40)
#define MAXF2 512  // cap |F2| (actual ~225)
#define MAXF3 64   // cap |F3| (actual ~16)
#define NKC 16     // k-chunks for the embedding GEMM
#define RELU(x) fmaxf((x), 0.f)

// ---------------- device scratch ----------------
__device__ int   g_e32;
__device__ int   g_indeg[NN];
__device__ int   g_adj[NN * ADJS];
__device__ int   g_inF3[NN], g_inF2[NN];
__device__ int   g_F3[MAXF3], g_F2[MAXF2];
__device__ int   g_slotF2[NN], g_slotF3[NN];
__device__ int   g_slot2cls[NKPAD];
__device__ int   g_nF3, g_nF2, g_nk;
__device__ float g_cnt2[MAXF2 * NKPAD];       // batch-invariant class-count matrix
__device__ float g_Epart[NKC * BB * CC];      // embedding partial sums (k-split)
__device__ float g_h2[BB * MAXF2 * CC];       // per-graph h2

// ---------------- preprocessing ----------------
__global__ void k_init(const void* ei) {
    int t = blockIdx.x * blockDim.x + threadIdx.x;
    int nth = gridDim.x * blockDim.x;
    for (int i = t; i < NN; i += nth) { g_indeg[i] = 0; g_inF3[i] = 0; g_inF2[i] = 0; }
    for (int i = t; i < MAXF2 * NKPAD; i += nth) g_cnt2[i] = 0.f;
    if (t == 0) {
        g_nF3 = 0; g_nF2 = 0;
        // dtype detect: int32 data reinterpreted as int64 gives out-of-range values
        const long long* p = (const long long*)ei;
        int e32 = 0;
        for (int j = 0; j < 16; j++) { long long v = p[j]; if (v < 0 || v >= (long long)NN) e32 = 1; }
        g_e32 = e32;
    }
}

__global__ void k_edges(const void* ei) {
    int t = blockIdx.x * blockDim.x + threadIdx.x;
    int nth = gridDim.x * blockDim.x;
    int e32 = g_e32;
    const int* pi = (const int*)ei;
    const long long* pl = (const long long*)ei;
    for (int e = t; e < EE; e += nth) {
        int sv = e32 ? pi[e] : (int)pl[e];
        int dv = e32 ? pi[EE + e] : (int)pl[EE + e];
        int pos = atomicAdd(&g_indeg[dv], 1);
        if (pos < ADJS) g_adj[dv * ADJS + pos] = sv;
        if (dv == 0) {
            if (atomicExch(&g_inF3[sv], 1) == 0) {
                int sl = atomicAdd(&g_nF3, 1);
                if (sl < MAXF3) { g_F3[sl] = sv; g_slotF3[sv] = sl; }
                else g_slotF3[sv] = MAXF3 - 1;
            }
        }
    }
}

__global__ void __launch_bounds__(1024) k_sets() {
    __shared__ int s_used[KMAXC], s_cls2slot[KMAXC];
    int t = threadIdx.x;  // == NN
    if (t < KMAXC) s_used[t] = 0;
    __syncthreads();
    { int k = min(g_indeg[t], KMAXC - 1); s_used[k] = 1; }
    __syncthreads();
    if (t == 0) {   // deterministic class compaction
        int nk = 0;
        for (int k = 0; k < KMAXC; k++) if (s_used[k]) {
            s_cls2slot[k] = (nk < NKPAD) ? nk : NKPAD - 1;
            if (nk < NKPAD) g_slot2cls[nk] = k;
            nk++;
        }
        g_nk = min(nk, NKPAD);
    }
    __syncthreads();
    // F2 = distinct in-neighbors of F3
    int nf3 = min(g_nF3, MAXF3);
    for (int idx = t; idx < nf3 * ADJS; idx += 1024) {
        int w = g_F3[idx / ADJS], j = idx % ADJS;
        if (j < min(g_indeg[w], ADJS)) {
            int src = g_adj[w * ADJS + j];
            if (atomicExch(&g_inF2[src], 1) == 0) {
                int sl = atomicAdd(&g_nF2, 1);
                if (sl < MAXF2) { g_F2[sl] = src; g_slotF2[src] = sl; }
                else g_slotF2[src] = MAXF2 - 1;
            }
        }
    }
    __syncthreads();
    // class-count matrix for F2 nodes (integer counts -> exact in float)
    int nf2 = min(g_nF2, MAXF2);
    for (int idx = t; idx < nf2 * ADJS; idx += 1024) {
        int sl = idx / ADJS, j = idx % ADJS;
        int u = g_F2[sl];
        if (j < min(g_indeg[u], ADJS)) {
            int src = g_adj[u * ADJS + j];
            int cs = s_cls2slot[min(g_indeg[src], KMAXC - 1)];
            atomicAdd(&g_cnt2[sl * NKPAD + cs], 1.f);
        }
    }
}

// ---------------- embedding partials: grid (4 strips, 16 kchunks), W_emb read ONCE ----------------
__global__ void __launch_bounds__(256) k_embedA(const float* __restrict__ x,
                                                const float* __restrict__ W_emb) {
    __shared__ float xs[BB * 64];   // x[0..63][k0..k0+63]
    int strip = blockIdx.x, kc = blockIdx.y;
    int t = threadIdx.x;
    int k0 = kc * 64;
    for (int i = t; i < BB * 16; i += 256) {   // 1024 float4
        int b = i >> 4, j4 = (i & 15) * 4;
        *(float4*)&xs[b * 64 + j4] = *(const float4*)&x[b * DD + k0 + j4];
    }
    __syncthreads();
    int col = strip * 32 + (t & 31);
    int b0 = (t >> 5) * 8;
    float acc[8] = {};
    for (int k = 0; k < 64; k += 4) {
        float w0 = W_emb[(k0 + k + 0) * CC + col];
        float w1 = W_emb[(k0 + k + 1) * CC + col];
        float w2 = W_emb[(k0 + k + 2) * CC + col];
        float w3 = W_emb[(k0 + k + 3) * CC + col];
#pragma unroll
        for (int r = 0; r < 8; r++) {
            float4 a = *(float4*)&xs[(b0 + r) * 64 + k];
            acc[r] += a.x * w0 + a.y * w1 + a.z * w2 + a.w * w3;
        }
    }
#pragma unroll
    for (int r = 0; r < 8; r++)
        g_Epart[(kc * BB + b0 + r) * CC + col] = acc[r];
}

// ---------------- mid: e-reduce -> hw0 -> A1 -> hw1c(half) -> h2(half), grid (64, 2) ----------------
// smem floats: sWh 8192 | sA1 8192 | sH1 4096 | sCnt 4096 | e_s 128 | hw0f 128 | part 256 | bcs 128
#define SMEM_MID ((8192 + 8192 + 4096 + 4096 + 128 + 128 + 256 + 128) * 4)
__global__ void __launch_bounds__(256, 1) k_mid(const float* __restrict__ W_conv,
                                                const float* __restrict__ b_conv,
                                                const float* __restrict__ b_emb) {
    extern __shared__ float S[];
    float* sWh  = S;           // [128][64]  W_conv columns n0..n0+63
    float* sA1  = S + 8192;    // [64][128]
    float* sH1  = S + 16384;   // [64][64]   hw1c half
    float* sCnt = S + 20480;   // [64][64]
    float* e_s  = S + 24576;
    float* hw0f = S + 24704;
    float* part = S + 24832;
    float* bcs  = S + 25088;
    __shared__ int scls[NKPAD];

    int b = blockIdx.x, n0 = blockIdx.y * 64;
    int t = threadIdx.x, warp = t >> 5, lane = t & 31;
    int nk = g_nk, nF2 = min(g_nF2, MAXF2);
    int nk4 = (nk + 3) & ~3;

    if (t < CC) {   // e = relu(sum of 16 k-partials + b_emb)
        float s = b_emb[t];
#pragma unroll
        for (int kc = 0; kc < NKC; kc++) s += g_Epart[(kc * BB + b) * CC + t];
        e_s[t] = RELU(s);
        bcs[t] = b_conv[t];
    }
    if (t < NKPAD) scls[t] = g_slot2cls[t];
#pragma unroll
    for (int q = 0; q < 8; q++) {          // W half: 128x64 = 2048 float4
        int idx = t + q * 256;
        int row = idx >> 4, c4 = (idx & 15) * 4;
        *(float4*)&sWh[row * 64 + c4] = *(const float4*)&W_conv[row * CC + n0 + c4];
    }
    __syncthreads();

    // hw0 full (redundant per half), K split over 2 thread groups
    {
        int c = t & 127, kh = t >> 7;
        float a = 0.f;
#pragma unroll 8
        for (int j = kh * 64; j < kh * 64 + 64; j++)
            a += e_s[j] * W_conv[j * CC + c];
        part[t] = a;
    }
    __syncthreads();
    if (t < CC) hw0f[t] = part[t] + part[t + 128];
    __syncthreads();

    // A1[slot][k] = relu(cls*hw0[k] + b) (rows >= nk zero)
    for (int idx = t; idx < NKPAD * CC; idx += 256) {
        int slot = idx >> 7, k = idx & 127;
        float v = 0.f;
        if (slot < nk) v = RELU((float)scls[slot] * hw0f[k] + bcs[k]);
        sA1[idx] = v;
    }
    __syncthreads();

    // hw1c half: rows 0..ceil8(nk), [rows x 64] = sA1 @ sWh, K=128
    {
        int rb = warp * 8, cb = lane * 2;
        if (rb < nk) {
            float acc[8][2] = {};
            for (int k = 0; k < CC; k += 4) {
                float2 wv0 = *(float2*)&sWh[(k + 0) * 64 + cb];
                float2 wv1 = *(float2*)&sWh[(k + 1) * 64 + cb];
                float2 wv2 = *(float2*)&sWh[(k + 2) * 64 + cb];
                float2 wv3 = *(float2*)&sWh[(k + 3) * 64 + cb];
#pragma unroll
                for (int r = 0; r < 8; r++) {
                    float4 a = *(float4*)&sA1[(rb + r) * CC + k];
                    acc[r][0] += a.x * wv0.x + a.y * wv1.x + a.z * wv2.x + a.w * wv3.x;
                    acc[r][1] += a.x * wv0.y + a.y * wv1.y + a.z * wv2.y + a.w * wv3.y;
                }
            }
#pragma unroll
            for (int r = 0; r < 8; r++)
                *(float2*)&sH1[(rb + r) * 64 + cb] = make_float2(acc[r][0], acc[r][1]);
        }
    }
    __syncthreads();

    // h2 half: relu(Cnt @ hw1c_half + b), K bounded by nk4, chunks of 64 rows
    {
        int rb = warp * 8, cb = lane * 2;
        float2 bc2 = *(float2*)&bcs[n0 + cb];
        for (int r0 = 0; r0 < nF2; r0 += 64) {
#pragma unroll
            for (int q = 0; q < 4; q++)
                ((float4*)sCnt)[t + q * 256] = ((const float4*)&g_cnt2[r0 * NKPAD])[t + q * 256];
            __syncthreads();
            float acc[8][2] = {};
            for (int k = 0; k < nk4; k += 4) {
                float2 wv0 = *(float2*)&sH1[(k + 0) * 64 + cb];
                float2 wv1 = *(float2*)&sH1[(k + 1) * 64 + cb];
                float2 wv2 = *(float2*)&sH1[(k + 2) * 64 + cb];
                float2 wv3 = *(float2*)&sH1[(k + 3) * 64 + cb];
#pragma unroll
                for (int r = 0; r < 8; r++) {
                    float4 a = *(float4*)&sCnt[(rb + r) * NKPAD + k];
                    acc[r][0] += a.x * wv0.x + a.y * wv1.x + a.z * wv2.x + a.w * wv3.x;
                    acc[r][1] += a.x * wv0.y + a.y * wv1.y + a.z * wv2.y + a.w * wv3.y;
                }
            }
#pragma unroll
            for (int r = 0; r < 8; r++) {
                int row = r0 + rb + r;
                if (row < nF2)
                    *(float2*)&g_h2[(((unsigned)b << 9) + row) * CC + n0 + cb] =
                        make_float2(RELU(acc[r][0] + bc2.x), RELU(acc[r][1] + bc2.y));
            }
            __syncthreads();
        }
    }
}

// ---------------- tail: h3 at F3, conv4 at node0, classifier; grid (64) ----------------
// smem floats: sW 16384 | h3s 8192 | rowbuf 1024 | agg 128 | red 8 | bcs 128
#define SMEM_TAIL ((16384 + 8192 + 1024 + 128 + 8 + 128) * 4)
__global__ void __launch_bounds__(256, 1) k_tail(const float* __restrict__ W_conv,
                                                 const float* __restrict__ b_conv,
                                                 const float* __restrict__ Wcls,
                                                 const float* __restrict__ bcls,
                                                 float* __restrict__ out) {
    extern __shared__ float S[];
    float* sW     = S;
    float* h3s    = S + 16384;   // [64][128]
    float* rowbuf = S + 24576;   // [8][128]
    float* agg    = S + 25600;
    float* red    = S + 25728;
    float* bcs    = S + 25736;
    int b = blockIdx.x, t = threadIdx.x, warp = t >> 5, lane = t & 31;
    int nF3 = min(g_nF3, MAXF3);
#pragma unroll
    for (int q = 0; q < 16; q++)
        ((float4*)sW)[t + q * 256] = ((const float4*)W_conv)[t + q * 256];
    if (t < CC) bcs[t] = b_conv[t];
    __syncthreads();

    for (int f = warp; f < nF3; f += 8) {
        int node = g_F3[f];
        int deg = min(g_indeg[node], ADJS);
        float a0 = 0.f, a1 = 0.f, a2 = 0.f, a3 = 0.f;
        for (int j = 0; j < deg; j++) {
            int src = g_adj[node * ADJS + j];
            const float* p = &g_h2[(((unsigned)b << 9) + g_slotF2[src]) * CC];
            a0 += p[lane]; a1 += p[lane + 32]; a2 += p[lane + 64]; a3 += p[lane + 96];
        }
        float* rb = &rowbuf[warp * CC];
        rb[lane] = a0; rb[lane + 32] = a1; rb[lane + 64] = a2; rb[lane + 96] = a3;
        __syncwarp();
        float y0 = 0.f, y1 = 0.f, y2 = 0.f, y3 = 0.f;
#pragma unroll 4
        for (int j = 0; j < CC; j++) {
            float r = rb[j];
            const float* wr = &sW[j * CC];
            y0 += r * wr[lane]; y1 += r * wr[lane + 32];
            y2 += r * wr[lane + 64]; y3 += r * wr[lane + 96];
        }
        h3s[f * CC + lane]      = RELU(y0 + bcs[lane]);
        h3s[f * CC + lane + 32] = RELU(y1 + bcs[lane + 32]);
        h3s[f * CC + lane + 64] = RELU(y2 + bcs[lane + 64]);
        h3s[f * CC + lane + 96] = RELU(y3 + bcs[lane + 96]);
        __syncwarp();
    }
    __syncthreads();

    if (t < CC) {
        int deg0 = min(g_indeg[0], ADJS);
        float a = 0.f;
        for (int j = 0; j < deg0; j++)
            a += h3s[g_slotF3[g_adj[j]] * CC + t];
        agg[t] = a;
    }
    __syncthreads();
    if (t < CC) {
        float y = 0.f;
#pragma unroll 8
        for (int j = 0; j < CC; j++) y += agg[j] * sW[j * CC + t];
        y = RELU(y + bcs[t]);
        float v = y * Wcls[t];
#pragma unroll
        for (int o = 16; o; o >>= 1) v += __shfl_xor_sync(0xffffffffu, v, o);
        if (lane == 0) red[warp] = v;
    }
    __syncthreads();
    if (t == 0) out[b] = red[0] + red[1] + red[2] + red[3] + bcls[0];
}

// ---------------- launch ----------------
extern "C" void kernel_launch(void* const* d_in, const int* in_sizes, int n_in,
                              void* d_out, int out_size) {
    const float* x      = (const float*)d_in[0];
    const void*  ei     = d_in[1];
    const float* W_emb  = (const float*)d_in[2];
    const float* b_emb  = (const float*)d_in[3];
    const float* W_conv = (const float*)d_in[4];
    const float* b_conv = (const float*)d_in[5];
    const float* W_cls  = (const float*)d_in[6];
    const float* b_cls  = (const float*)d_in[7];
    float* out = (float*)d_out;

    (void)cudaFuncSetAttribute(k_mid,  cudaFuncAttributeMaxDynamicSharedMemorySize, SMEM_MID);
    (void)cudaFuncSetAttribute(k_tail, cudaFuncAttributeMaxDynamicSharedMemorySize, SMEM_TAIL);

    k_init<<<16, 256>>>(ei);
    k_edges<<<16, 256>>>(ei);
    k_embedA<<<dim3(4, NKC), 256>>>(x, W_emb);
    k_sets<<<1, 1024>>>();
    k_mid<<<dim3(BB, 2), 256, SMEM_MID>>>(W_conv, b_conv, b_emb);
    k_tail<<<BB, 256, SMEM_TAIL>>>(W_conv, b_conv, W_cls, b_cls, out);
}